// round 1
// baseline (speedup 1.0000x reference)
#include <cuda_runtime.h>
#include <math.h>

#define D      512
#define T      256
#define TOPK   8
#define NPAIR  2048
#define NEXP   16
#define MAXH   2560
#define NSCORE 4096

// ---------------- scratch (static device allocations; no cudaMalloc) ----------
__device__ float g_h1[T * D];            // router fc1 out
__device__ float g_h2[T * 256];          // router fc2 out
__device__ float g_scores[T * NSCORE];   // router fc3 out
__device__ float g_preu[NPAIR * D];      // pre GEMM out (pre-LN)
__device__ float g_xin[NPAIR * D];       // pre LN+act out (MLP input)
__device__ float g_hmid[NPAIR * MAXH];   // mlp hidden
__device__ float g_y[NPAIR * D];         // mlp out
__device__ float g_z[NPAIR * D];         // post GEMM out
__device__ float g_w[NPAIR];             // per-pair weight
__device__ int   g_prei[NPAIR];
__device__ int   g_posti[NPAIR];
__device__ int   g_cnt[48];              // [0:16) pre, [16:32) mlp, [32:48) post
__device__ int   g_rows[48 * NPAIR];     // per-expert pair lists

// ---------------- activations ------------------------------------------------
__device__ __forceinline__ float actf(int a, float v) {
    switch (a) {
        case 0: return 0.5f * v * (1.0f + erff(v * 0.7071067811865476f)); // exact gelu
        case 1: return fmaxf(v, 0.0f);                                    // relu
        case 2: return tanhf(v);                                          // tanh
        default: return v / (1.0f + expf(-v));                            // silu
    }
}

// ---------------- generic tiled GEMM -----------------------------------------
// C[crow, n] = act( sum_k A[arow, k] * B[e][k, n] + bias[e][n] )
// BM=BN=64, BK=16, 256 threads, 4x4 microtile per thread.
// Gathered mode: rows list gives pair ids; arow = pair >> gshift; crow = pair.
// varN/varK: dimension is he(e) = 512*(2 + e/4).
struct GArgs {
    const float* A; int lda;
    const float* B; long bStride; int ldb;
    const float* bias; int biasStride;
    float* C; int ldc;
    int M, N, K;
    const int* rows; const int* cnt;   // base for this group (16 experts)
    int gshift;
    int varN, varK;
    int act;  // 0 none, 1..4 fixed (act-1), 5 per-expert e&3
};

__global__ __launch_bounds__(256) void gemm_k(GArgs g) {
    const int e  = blockIdx.z;
    const int Me = g.cnt ? g.cnt[e] : g.M;
    const int he = 512 * (2 + (e >> 2));
    const int Ne = g.varN ? he : g.N;
    const int Ke = g.varK ? he : g.K;
    const int n0 = blockIdx.x * 64;
    if (n0 >= Ne) return;

    const float* B  = g.B + (long)e * g.bStride;
    const int*   rl = g.rows ? (g.rows + e * NPAIR) : nullptr;

    __shared__ __align__(16) float As[16][64];
    __shared__ __align__(16) float Bs[16][64];

    const int tid = threadIdx.x;
    const int tx = tid & 15, ty = tid >> 4;
    const int lr = tid >> 2;          // A load row 0..63
    const int lk = (tid & 3) * 4;     // A load k offset {0,4,8,12}
    const int kb = tid >> 4;          // B load k row 0..15
    const int cb = (tid & 15) * 4;    // B load col

    const int aAct = (g.act == 5) ? (e & 3) : (g.act - 1);

    for (int m0 = blockIdx.y * 64; m0 < Me; m0 += gridDim.y * 64) {
        const bool mv = (m0 + lr) < Me;
        long arow;
        if (rl) {
            int pr = mv ? rl[m0 + lr] : 0;
            arow = (long)(pr >> g.gshift);
        } else {
            arow = m0 + lr;
        }
        const float* Ap = g.A + arow * (long)g.lda + lk;

        float acc[4][4];
#pragma unroll
        for (int i = 0; i < 4; i++)
#pragma unroll
            for (int j = 0; j < 4; j++) acc[i][j] = 0.0f;

        for (int k0 = 0; k0 < Ke; k0 += 16) {
            float4 av = mv ? *(const float4*)(Ap + k0) : make_float4(0.f, 0.f, 0.f, 0.f);
            float4 bv = *(const float4*)(B + (long)(k0 + kb) * g.ldb + n0 + cb);
            __syncthreads();  // previous tile's compute finished
            As[lk + 0][lr] = av.x;
            As[lk + 1][lr] = av.y;
            As[lk + 2][lr] = av.z;
            As[lk + 3][lr] = av.w;
            *(float4*)&Bs[kb][cb] = bv;
            __syncthreads();
#pragma unroll
            for (int kk = 0; kk < 16; kk++) {
                float4 a4 = *(const float4*)&As[kk][ty * 4];
                float4 b4 = *(const float4*)&Bs[kk][tx * 4];
                float aa[4] = {a4.x, a4.y, a4.z, a4.w};
                float bb[4] = {b4.x, b4.y, b4.z, b4.w};
#pragma unroll
                for (int i = 0; i < 4; i++)
#pragma unroll
                    for (int j = 0; j < 4; j++) acc[i][j] += aa[i] * bb[j];
            }
        }

        float4 b4 = *(const float4*)(g.bias + (long)e * g.biasStride + n0 + tx * 4);
        float bb[4] = {b4.x, b4.y, b4.z, b4.w};
#pragma unroll
        for (int i = 0; i < 4; i++) {
            int m = m0 + ty * 4 + i;
            if (m >= Me) break;
            long cr = rl ? (long)rl[m] : m;
            float vals[4];
#pragma unroll
            for (int j = 0; j < 4; j++) {
                float v = acc[i][j] + bb[j];
                if (aAct >= 0) v = actf(aAct, v);
                vals[j] = v;
            }
            *(float4*)(g.C + cr * (long)g.ldc + n0 + tx * 4) =
                make_float4(vals[0], vals[1], vals[2], vals[3]);
        }
    }
}

// ---------------- zero counters ----------------------------------------------
__global__ void zero_k(int* cnt) {
    if (threadIdx.x < 48) cnt[threadIdx.x] = 0;
}

// ---------------- softmax + top-k + routing ----------------------------------
__global__ __launch_bounds__(256) void route_k(const float* scores, const float* temp,
                                               float* w, int* prei, int* posti,
                                               int* cnt, int* rows) {
    const int t = blockIdx.x, tid = threadIdx.x;
    __shared__ float sm[NSCORE];
    __shared__ float rv[256];
    __shared__ int   ri[256];

    const float invT = 1.0f / temp[0];
    for (int j = tid; j < NSCORE; j += 256) sm[j] = scores[t * NSCORE + j] * invT;
    __syncthreads();

    float mx = -3.4e38f;
    for (int j = tid; j < NSCORE; j += 256) mx = fmaxf(mx, sm[j]);
    rv[tid] = mx; __syncthreads();
    for (int s = 128; s > 0; s >>= 1) { if (tid < s) rv[tid] = fmaxf(rv[tid], rv[tid + s]); __syncthreads(); }
    const float gmax = rv[0]; __syncthreads();

    float sum = 0.0f;
    for (int j = tid; j < NSCORE; j += 256) sum += expf(sm[j] - gmax);
    rv[tid] = sum; __syncthreads();
    for (int s = 128; s > 0; s >>= 1) { if (tid < s) rv[tid] += rv[tid + s]; __syncthreads(); }
    const float gsum = rv[0]; __syncthreads();

    for (int k = 0; k < TOPK; k++) {
        float bv = -3.4e38f; int bi = NSCORE;
        for (int j = tid; j < NSCORE; j += 256) {
            float v = sm[j];
            if (v > bv || (v == bv && j < bi)) { bv = v; bi = j; }
        }
        rv[tid] = bv; ri[tid] = bi; __syncthreads();
        for (int s = 128; s > 0; s >>= 1) {
            if (tid < s) {
                float ov = rv[tid + s]; int oi = ri[tid + s];
                if (ov > rv[tid] || (ov == rv[tid] && oi < ri[tid])) { rv[tid] = ov; ri[tid] = oi; }
            }
            __syncthreads();
        }
        if (tid == 0) {
            int idx = ri[0];
            float prob = expf(rv[0] - gmax) / gsum;
            float ww = (prob >= 1e-6f) ? prob : 0.0f;
            int pair = t * TOPK + k;
            int pe = idx >> 8, rem = idx & 255, me = rem >> 4, oe = rem & 15;
            prei[pair] = pe; posti[pair] = oe; w[pair] = ww;
            int s0 = atomicAdd(&cnt[pe], 1);       rows[pe * NPAIR + s0] = pair;
            int s1 = atomicAdd(&cnt[16 + me], 1);  rows[(16 + me) * NPAIR + s1] = pair;
            int s2 = atomicAdd(&cnt[32 + oe], 1);  rows[(32 + oe) * NPAIR + s2] = pair;
            sm[idx] = -3.4e38f;
        }
        __syncthreads();
    }
}

// ---------------- pre-expert LN + act ----------------------------------------
__global__ __launch_bounds__(256) void prelnact_k(const float* U, const int* prei,
                                                  const float* g, const float* b, float* X) {
    const int p = blockIdx.x, tid = threadIdx.x;
    __shared__ float rv[256];
    const int e = prei[p];
    float u0 = U[p * D + tid], u1 = U[p * D + tid + 256];

    rv[tid] = u0 + u1; __syncthreads();
    for (int s = 128; s > 0; s >>= 1) { if (tid < s) rv[tid] += rv[tid + s]; __syncthreads(); }
    const float mean = rv[0] * (1.0f / D); __syncthreads();

    float d0 = u0 - mean, d1 = u1 - mean;
    rv[tid] = d0 * d0 + d1 * d1; __syncthreads();
    for (int s = 128; s > 0; s >>= 1) { if (tid < s) rv[tid] += rv[tid + s]; __syncthreads(); }
    const float rstd = rsqrtf(rv[0] * (1.0f / D) + 1e-5f);

    const int a = e & 3;
    X[p * D + tid]       = actf(a, d0 * rstd * g[e * D + tid]       + b[e * D + tid]);
    X[p * D + tid + 256] = actf(a, d1 * rstd * g[e * D + tid + 256] + b[e * D + tid + 256]);
}

// ---------------- post LN (even experts) + weighted reduce -------------------
__global__ __launch_bounds__(256) void final_k(const float* Z, const int* posti, const float* w,
                                               const float* g, const float* b, float* out) {
    const int t = blockIdx.x, tid = threadIdx.x;
    __shared__ float rv[256];
    float a0 = 0.0f, a1 = 0.0f;
    for (int k = 0; k < TOPK; k++) {
        const int pair = t * TOPK + k;
        const int e = posti[pair];
        const float ww = w[pair];
        float z0 = Z[pair * D + tid], z1 = Z[pair * D + tid + 256];
        if ((e & 1) == 0) {  // uniform per block
            rv[tid] = z0 + z1; __syncthreads();
            for (int s = 128; s > 0; s >>= 1) { if (tid < s) rv[tid] += rv[tid + s]; __syncthreads(); }
            const float mean = rv[0] * (1.0f / D); __syncthreads();
            float d0 = z0 - mean, d1 = z1 - mean;
            rv[tid] = d0 * d0 + d1 * d1; __syncthreads();
            for (int s = 128; s > 0; s >>= 1) { if (tid < s) rv[tid] += rv[tid + s]; __syncthreads(); }
            const float rstd = rsqrtf(rv[0] * (1.0f / D) + 1e-5f); __syncthreads();
            z0 = d0 * rstd * g[e * D + tid]       + b[e * D + tid];
            z1 = d1 * rstd * g[e * D + tid + 256] + b[e * D + tid + 256];
        }
        a0 += ww * z0; a1 += ww * z1;
    }
    out[t * D + tid] = a0;
    out[t * D + tid + 256] = a1;
}

// ---------------- launch -----------------------------------------------------
extern "C" void kernel_launch(void* const* d_in, const int* in_sizes, int n_in,
                              void* d_out, int out_size) {
    const float* x       = (const float*)d_in[0];
    const float* r_w1    = (const float*)d_in[1];
    const float* r_b1    = (const float*)d_in[2];
    const float* r_w2    = (const float*)d_in[3];
    const float* r_b2    = (const float*)d_in[4];
    const float* r_w3    = (const float*)d_in[5];
    const float* r_b3    = (const float*)d_in[6];
    const float* temp    = (const float*)d_in[7];
    const float* pre_w   = (const float*)d_in[8];
    const float* pre_b   = (const float*)d_in[9];
    const float* pre_g   = (const float*)d_in[10];
    const float* pre_be  = (const float*)d_in[11];
    const float* mlp_w1  = (const float*)d_in[12];
    const float* mlp_b1  = (const float*)d_in[13];
    const float* mlp_w2  = (const float*)d_in[14];
    const float* mlp_b2  = (const float*)d_in[15];
    const float* post_w  = (const float*)d_in[16];
    const float* post_b  = (const float*)d_in[17];
    const float* post_g  = (const float*)d_in[18];
    const float* post_be = (const float*)d_in[19];
    float* out = (float*)d_out;

    float *h1, *h2, *sc, *preu, *xin, *hmid, *y, *z, *w;
    int *prei, *posti, *cnt, *rows;
    cudaGetSymbolAddress((void**)&h1, g_h1);
    cudaGetSymbolAddress((void**)&h2, g_h2);
    cudaGetSymbolAddress((void**)&sc, g_scores);
    cudaGetSymbolAddress((void**)&preu, g_preu);
    cudaGetSymbolAddress((void**)&xin, g_xin);
    cudaGetSymbolAddress((void**)&hmid, g_hmid);
    cudaGetSymbolAddress((void**)&y, g_y);
    cudaGetSymbolAddress((void**)&z, g_z);
    cudaGetSymbolAddress((void**)&w, g_w);
    cudaGetSymbolAddress((void**)&prei, g_prei);
    cudaGetSymbolAddress((void**)&posti, g_posti);
    cudaGetSymbolAddress((void**)&cnt, g_cnt);
    cudaGetSymbolAddress((void**)&rows, g_rows);

    zero_k<<<1, 64>>>(cnt);

    // router fc1: (256x512) @ (512x512) + gelu
    {
        GArgs a = {x, D, r_w1, 0, 512, r_b1, 0, h1, 512,
                   T, 512, 512, nullptr, nullptr, 0, 0, 0, 1};
        gemm_k<<<dim3(8, 4, 1), 256>>>(a);
    }
    // router fc2: (256x512) @ (512x256) + gelu
    {
        GArgs a = {h1, 512, r_w2, 0, 256, r_b2, 0, h2, 256,
                   T, 256, 512, nullptr, nullptr, 0, 0, 0, 1};
        gemm_k<<<dim3(4, 4, 1), 256>>>(a);
    }
    // router fc3: (256x256) @ (256x4096)
    {
        GArgs a = {h2, 256, r_w3, 0, NSCORE, r_b3, 0, sc, NSCORE,
                   T, NSCORE, 256, nullptr, nullptr, 0, 0, 0, 0};
        gemm_k<<<dim3(64, 4, 1), 256>>>(a);
    }

    route_k<<<T, 256>>>(sc, temp, w, prei, posti, cnt, rows);

    // pre experts: gathered GEMM, A row = pair>>3 (token), C row = pair
    {
        GArgs a = {x, D, pre_w, (long)D * D, D, pre_b, D, preu, D,
                   NPAIR, D, D, rows, cnt, 3, 0, 0, 0};
        gemm_k<<<dim3(8, 4, NEXP), 256>>>(a);
    }
    prelnact_k<<<NPAIR, 256>>>(preu, prei, pre_g, pre_be, xin);

    // mlp fc1: gathered, N = he(e), per-expert act
    {
        GArgs a = {xin, D, mlp_w1, (long)D * MAXH, MAXH, mlp_b1, MAXH, hmid, MAXH,
                   NPAIR, MAXH, D, rows + 16 * NPAIR, cnt + 16, 0, 1, 0, 5};
        gemm_k<<<dim3(40, 4, NEXP), 256>>>(a);
    }
    // mlp fc2: gathered, K = he(e)
    {
        GArgs a = {hmid, MAXH, mlp_w2, (long)MAXH * D, D, mlp_b2, D, y, D,
                   NPAIR, D, MAXH, rows + 16 * NPAIR, cnt + 16, 0, 0, 1, 0};
        gemm_k<<<dim3(8, 4, NEXP), 256>>>(a);
    }
    // post experts: gathered
    {
        GArgs a = {y, D, post_w, (long)D * D, D, post_b, D, z, D,
                   NPAIR, D, D, rows + 32 * NPAIR, cnt + 32, 0, 0, 0, 0};
        gemm_k<<<dim3(8, 4, NEXP), 256>>>(a);
    }

    final_k<<<T, 256>>>(z, posti, w, post_g, post_be, out);
}

// round 2
// speedup vs baseline: 2.3975x; 2.3975x over previous
#include <cuda_runtime.h>
#include <math.h>

#define D      512
#define T      256
#define TOPK   8
#define NPAIR  2048
#define NEXP   16
#define MAXH   2560
#define NSCORE 4096

// ---------------- scratch (static device allocations; no cudaMalloc) ----------
__device__ float g_h1[T * D];            // router fc1 out
__device__ float g_h2[T * 256];          // router fc2 out
__device__ float g_scores[T * NSCORE];   // router fc3 out
__device__ float g_preu[NPAIR * D];      // pre GEMM out (pre-LN)
__device__ float g_xin[NPAIR * D];       // pre LN+act out (MLP input)
__device__ float g_hmid[NPAIR * MAXH];   // mlp hidden
__device__ float g_y[NPAIR * D];         // mlp out
__device__ float g_z[NPAIR * D];         // post GEMM out
__device__ float g_w[NPAIR];             // per-pair weight
__device__ int   g_prei[NPAIR];
__device__ int   g_posti[NPAIR];
__device__ int   g_cnt[48];              // [0:16) pre, [16:32) mlp, [32:48) post
__device__ int   g_rows[48 * NPAIR];     // per-expert pair lists

// ---------------- activations ------------------------------------------------
__device__ __forceinline__ float actf(int a, float v) {
    switch (a) {
        case 0: return 0.5f * v * (1.0f + erff(v * 0.7071067811865476f)); // exact gelu
        case 1: return fmaxf(v, 0.0f);                                    // relu
        case 2: return tanhf(v);                                          // tanh
        default: return v / (1.0f + expf(-v));                            // silu
    }
}

__device__ __forceinline__ unsigned f2tf32(float f) {
    unsigned r;
    asm("cvt.rna.tf32.f32 %0, %1;" : "=r"(r) : "f"(f));
    return r;
}

// ---------------- fp32 SIMT tiled GEMM (router only, exact) ------------------
struct GArgs {
    const float* A; int lda;
    const float* B; long bStride; int ldb;
    const float* bias; int biasStride;
    float* C; int ldc;
    int M, N, K;
    const int* rows; const int* cnt;
    int gshift;
    int varN, varK;
    int act;  // 0 none, 1..4 fixed (act-1), 5 per-expert e&3
};

__global__ __launch_bounds__(256) void gemm_k(GArgs g) {
    const int e  = blockIdx.z;
    const int Me = g.cnt ? g.cnt[e] : g.M;
    const int he = 512 * (2 + (e >> 2));
    const int Ne = g.varN ? he : g.N;
    const int Ke = g.varK ? he : g.K;
    const int n0 = blockIdx.x * 64;
    if (n0 >= Ne) return;

    const float* B  = g.B + (long)e * g.bStride;
    const int*   rl = g.rows ? (g.rows + e * NPAIR) : nullptr;

    __shared__ __align__(16) float As[16][64];
    __shared__ __align__(16) float Bs[16][64];

    const int tid = threadIdx.x;
    const int tx = tid & 15, ty = tid >> 4;
    const int lr = tid >> 2;
    const int lk = (tid & 3) * 4;
    const int kb = tid >> 4;
    const int cb = (tid & 15) * 4;

    const int aAct = (g.act == 5) ? (e & 3) : (g.act - 1);

    for (int m0 = blockIdx.y * 64; m0 < Me; m0 += gridDim.y * 64) {
        const bool mv = (m0 + lr) < Me;
        long arow;
        if (rl) {
            int pr = mv ? rl[m0 + lr] : 0;
            arow = (long)(pr >> g.gshift);
        } else {
            arow = m0 + lr;
        }
        const float* Ap = g.A + arow * (long)g.lda + lk;

        float acc[4][4];
#pragma unroll
        for (int i = 0; i < 4; i++)
#pragma unroll
            for (int j = 0; j < 4; j++) acc[i][j] = 0.0f;

        for (int k0 = 0; k0 < Ke; k0 += 16) {
            float4 av = mv ? *(const float4*)(Ap + k0) : make_float4(0.f, 0.f, 0.f, 0.f);
            float4 bv = *(const float4*)(B + (long)(k0 + kb) * g.ldb + n0 + cb);
            __syncthreads();
            As[lk + 0][lr] = av.x;
            As[lk + 1][lr] = av.y;
            As[lk + 2][lr] = av.z;
            As[lk + 3][lr] = av.w;
            *(float4*)&Bs[kb][cb] = bv;
            __syncthreads();
#pragma unroll
            for (int kk = 0; kk < 16; kk++) {
                float4 a4 = *(const float4*)&As[kk][ty * 4];
                float4 b4 = *(const float4*)&Bs[kk][tx * 4];
                float aa[4] = {a4.x, a4.y, a4.z, a4.w};
                float bb[4] = {b4.x, b4.y, b4.z, b4.w};
#pragma unroll
                for (int i = 0; i < 4; i++)
#pragma unroll
                    for (int j = 0; j < 4; j++) acc[i][j] += aa[i] * bb[j];
            }
        }

        float4 b4 = *(const float4*)(g.bias + (long)e * g.biasStride + n0 + tx * 4);
        float bb[4] = {b4.x, b4.y, b4.z, b4.w};
#pragma unroll
        for (int i = 0; i < 4; i++) {
            int m = m0 + ty * 4 + i;
            if (m >= Me) break;
            long cr = rl ? (long)rl[m] : m;
            float vals[4];
#pragma unroll
            for (int j = 0; j < 4; j++) {
                float v = acc[i][j] + bb[j];
                if (aAct >= 0) v = actf(aAct, v);
                vals[j] = v;
            }
            *(float4*)(g.C + cr * (long)g.ldc + n0 + tx * 4) =
                make_float4(vals[0], vals[1], vals[2], vals[3]);
        }
    }
}

// ---------------- tf32 tensor-core grouped GEMM (experts) --------------------
// Block 64x64, BK=16, 128 threads = 4 warps in 2x2, each warp 32x32
// via 2(m) x 4(n) m16n8k8 tf32 mma, fp32 accumulate.
__global__ __launch_bounds__(128) void tgemm_k(GArgs g) {
    const int e  = blockIdx.z;
    const int Me = g.cnt[e];
    const int he = 512 * (2 + (e >> 2));
    const int Ne = g.varN ? he : g.N;
    const int Ke = g.varK ? he : g.K;
    const int n0 = blockIdx.x * 64;
    if (n0 >= Ne) return;

    const float* B  = g.B + (long)e * g.bStride;
    const int*   rl = g.rows + e * NPAIR;

    __shared__ unsigned As[16][68];  // [k][m]
    __shared__ unsigned Bs[16][68];  // [k][n]

    const int tid  = threadIdx.x;
    const int warp = tid >> 5;
    const int lane = tid & 31;
    const int grp  = lane >> 2;      // 0..7
    const int t4   = lane & 3;       // 0..3
    const int wm   = warp >> 1;      // 0..1
    const int wn   = warp & 1;       // 0..1

    // A staging: thread loads 2 float4 of one row
    const int a_row = tid >> 1;              // 0..63
    const int a_q0  = (tid & 1) * 2;         // quad base 0 or 2

    const int aAct = (g.act == 5) ? (e & 3) : (g.act - 1);

    for (int m0 = blockIdx.y * 64; m0 < Me; m0 += gridDim.y * 64) {
        const bool mv = (m0 + a_row) < Me;
        long arow = 0;
        if (mv) arow = (long)(rl[m0 + a_row] >> g.gshift);
        const float* Ap = g.A + arow * (long)g.lda;

        float acc[2][4][4];
#pragma unroll
        for (int mi = 0; mi < 2; mi++)
#pragma unroll
            for (int ni = 0; ni < 4; ni++)
#pragma unroll
                for (int c = 0; c < 4; c++) acc[mi][ni][c] = 0.0f;

        for (int k0 = 0; k0 < Ke; k0 += 16) {
            // stage A (2 float4 per thread) and B (2 float4 per thread) in regs
            float4 av[2];
#pragma unroll
            for (int i = 0; i < 2; i++) {
                int kk = (a_q0 + i) * 4;
                av[i] = mv ? *(const float4*)(Ap + k0 + kk)
                           : make_float4(0.f, 0.f, 0.f, 0.f);
            }
            float4 bv[2];
            int bk[2], bn[2];
#pragma unroll
            for (int i = 0; i < 2; i++) {
                int idx = tid + i * 128;
                bk[i] = idx >> 4;
                bn[i] = (idx & 15) * 4;
                bv[i] = *(const float4*)(B + (long)(k0 + bk[i]) * g.ldb + n0 + bn[i]);
            }
            __syncthreads();
#pragma unroll
            for (int i = 0; i < 2; i++) {
                int kk = (a_q0 + i) * 4;
                As[kk + 0][a_row] = f2tf32(av[i].x);
                As[kk + 1][a_row] = f2tf32(av[i].y);
                As[kk + 2][a_row] = f2tf32(av[i].z);
                As[kk + 3][a_row] = f2tf32(av[i].w);
            }
#pragma unroll
            for (int i = 0; i < 2; i++) {
                Bs[bk[i]][bn[i] + 0] = f2tf32(bv[i].x);
                Bs[bk[i]][bn[i] + 1] = f2tf32(bv[i].y);
                Bs[bk[i]][bn[i] + 2] = f2tf32(bv[i].z);
                Bs[bk[i]][bn[i] + 3] = f2tf32(bv[i].w);
            }
            __syncthreads();

#pragma unroll
            for (int ks = 0; ks < 2; ks++) {
                const int kk = ks * 8;
                unsigned a[2][4], b[4][2];
#pragma unroll
                for (int mi = 0; mi < 2; mi++) {
                    int mr = wm * 32 + mi * 16 + grp;
                    a[mi][0] = As[kk + t4][mr];
                    a[mi][1] = As[kk + t4][mr + 8];
                    a[mi][2] = As[kk + t4 + 4][mr];
                    a[mi][3] = As[kk + t4 + 4][mr + 8];
                }
#pragma unroll
                for (int ni = 0; ni < 4; ni++) {
                    int nc = wn * 32 + ni * 8 + grp;
                    b[ni][0] = Bs[kk + t4][nc];
                    b[ni][1] = Bs[kk + t4 + 4][nc];
                }
#pragma unroll
                for (int mi = 0; mi < 2; mi++)
#pragma unroll
                    for (int ni = 0; ni < 4; ni++) {
                        float* c = acc[mi][ni];
                        asm volatile(
                            "mma.sync.aligned.m16n8k8.row.col.f32.tf32.tf32.f32 "
                            "{%0,%1,%2,%3}, {%4,%5,%6,%7}, {%8,%9}, {%0,%1,%2,%3};"
                            : "+f"(c[0]), "+f"(c[1]), "+f"(c[2]), "+f"(c[3])
                            : "r"(a[mi][0]), "r"(a[mi][1]), "r"(a[mi][2]), "r"(a[mi][3]),
                              "r"(b[ni][0]), "r"(b[ni][1]));
                    }
            }
        }

        // epilogue: bias + act + gathered store
        const float* bias = g.bias + (long)e * g.biasStride;
#pragma unroll
        for (int ni = 0; ni < 4; ni++) {
            int c = n0 + wn * 32 + ni * 8 + t4 * 2;
            float bb0 = bias[c], bb1 = bias[c + 1];
#pragma unroll
            for (int mi = 0; mi < 2; mi++) {
#pragma unroll
                for (int half = 0; half < 2; half++) {
                    int m = m0 + wm * 32 + mi * 16 + grp + half * 8;
                    if (m < Me) {
                        long cr = (long)rl[m];
                        float v0 = acc[mi][ni][half * 2 + 0] + bb0;
                        float v1 = acc[mi][ni][half * 2 + 1] + bb1;
                        if (aAct >= 0) { v0 = actf(aAct, v0); v1 = actf(aAct, v1); }
                        *(float2*)(g.C + cr * (long)g.ldc + c) = make_float2(v0, v1);
                    }
                }
            }
        }
        __syncthreads();
    }
}

// ---------------- zero counters ----------------------------------------------
__global__ void zero_k(int* cnt) {
    if (threadIdx.x < 48) cnt[threadIdx.x] = 0;
}

// ---------------- softmax + top-k + routing ----------------------------------
__global__ __launch_bounds__(256) void route_k(const float* scores, const float* temp,
                                               float* w, int* prei, int* posti,
                                               int* cnt, int* rows) {
    const int t = blockIdx.x, tid = threadIdx.x;
    __shared__ float sm[NSCORE];
    __shared__ float rv[256];
    __shared__ int   ri[256];

    const float invT = 1.0f / temp[0];
    for (int j = tid; j < NSCORE; j += 256) sm[j] = scores[t * NSCORE + j] * invT;
    __syncthreads();

    float mx = -3.4e38f;
    for (int j = tid; j < NSCORE; j += 256) mx = fmaxf(mx, sm[j]);
    rv[tid] = mx; __syncthreads();
    for (int s = 128; s > 0; s >>= 1) { if (tid < s) rv[tid] = fmaxf(rv[tid], rv[tid + s]); __syncthreads(); }
    const float gmax = rv[0]; __syncthreads();

    float sum = 0.0f;
    for (int j = tid; j < NSCORE; j += 256) sum += expf(sm[j] - gmax);
    rv[tid] = sum; __syncthreads();
    for (int s = 128; s > 0; s >>= 1) { if (tid < s) rv[tid] += rv[tid + s]; __syncthreads(); }
    const float gsum = rv[0]; __syncthreads();

    for (int k = 0; k < TOPK; k++) {
        float bv = -3.4e38f; int bi = NSCORE;
        for (int j = tid; j < NSCORE; j += 256) {
            float v = sm[j];
            if (v > bv || (v == bv && j < bi)) { bv = v; bi = j; }
        }
        rv[tid] = bv; ri[tid] = bi; __syncthreads();
        for (int s = 128; s > 0; s >>= 1) {
            if (tid < s) {
                float ov = rv[tid + s]; int oi = ri[tid + s];
                if (ov > rv[tid] || (ov == rv[tid] && oi < ri[tid])) { rv[tid] = ov; ri[tid] = oi; }
            }
            __syncthreads();
        }
        if (tid == 0) {
            int idx = ri[0];
            float prob = expf(rv[0] - gmax) / gsum;
            float ww = (prob >= 1e-6f) ? prob : 0.0f;
            int pair = t * TOPK + k;
            int pe = idx >> 8, rem = idx & 255, me = rem >> 4, oe = rem & 15;
            prei[pair] = pe; posti[pair] = oe; w[pair] = ww;
            int s0 = atomicAdd(&cnt[pe], 1);       rows[pe * NPAIR + s0] = pair;
            int s1 = atomicAdd(&cnt[16 + me], 1);  rows[(16 + me) * NPAIR + s1] = pair;
            int s2 = atomicAdd(&cnt[32 + oe], 1);  rows[(32 + oe) * NPAIR + s2] = pair;
            sm[idx] = -3.4e38f;
        }
        __syncthreads();
    }
}

// ---------------- pre-expert LN + act ----------------------------------------
__global__ __launch_bounds__(256) void prelnact_k(const float* U, const int* prei,
                                                  const float* g, const float* b, float* X) {
    const int p = blockIdx.x, tid = threadIdx.x;
    __shared__ float rv[256];
    const int e = prei[p];
    float u0 = U[p * D + tid], u1 = U[p * D + tid + 256];

    rv[tid] = u0 + u1; __syncthreads();
    for (int s = 128; s > 0; s >>= 1) { if (tid < s) rv[tid] += rv[tid + s]; __syncthreads(); }
    const float mean = rv[0] * (1.0f / D); __syncthreads();

    float d0 = u0 - mean, d1 = u1 - mean;
    rv[tid] = d0 * d0 + d1 * d1; __syncthreads();
    for (int s = 128; s > 0; s >>= 1) { if (tid < s) rv[tid] += rv[tid + s]; __syncthreads(); }
    const float rstd = rsqrtf(rv[0] * (1.0f / D) + 1e-5f);

    const int a = e & 3;
    X[p * D + tid]       = actf(a, d0 * rstd * g[e * D + tid]       + b[e * D + tid]);
    X[p * D + tid + 256] = actf(a, d1 * rstd * g[e * D + tid + 256] + b[e * D + tid + 256]);
}

// ---------------- post LN (even experts) + weighted reduce -------------------
__global__ __launch_bounds__(256) void final_k(const float* Z, const int* posti, const float* w,
                                               const float* g, const float* b, float* out) {
    const int t = blockIdx.x, tid = threadIdx.x;
    __shared__ float rv[256];
    float a0 = 0.0f, a1 = 0.0f;
    for (int k = 0; k < TOPK; k++) {
        const int pair = t * TOPK + k;
        const int e = posti[pair];
        const float ww = w[pair];
        float z0 = Z[pair * D + tid], z1 = Z[pair * D + tid + 256];
        if ((e & 1) == 0) {
            rv[tid] = z0 + z1; __syncthreads();
            for (int s = 128; s > 0; s >>= 1) { if (tid < s) rv[tid] += rv[tid + s]; __syncthreads(); }
            const float mean = rv[0] * (1.0f / D); __syncthreads();
            float d0 = z0 - mean, d1 = z1 - mean;
            rv[tid] = d0 * d0 + d1 * d1; __syncthreads();
            for (int s = 128; s > 0; s >>= 1) { if (tid < s) rv[tid] += rv[tid + s]; __syncthreads(); }
            const float rstd = rsqrtf(rv[0] * (1.0f / D) + 1e-5f); __syncthreads();
            z0 = d0 * rstd * g[e * D + tid]       + b[e * D + tid];
            z1 = d1 * rstd * g[e * D + tid + 256] + b[e * D + tid + 256];
        }
        a0 += ww * z0; a1 += ww * z1;
    }
    out[t * D + tid] = a0;
    out[t * D + tid + 256] = a1;
}

// ---------------- launch -----------------------------------------------------
extern "C" void kernel_launch(void* const* d_in, const int* in_sizes, int n_in,
                              void* d_out, int out_size) {
    const float* x       = (const float*)d_in[0];
    const float* r_w1    = (const float*)d_in[1];
    const float* r_b1    = (const float*)d_in[2];
    const float* r_w2    = (const float*)d_in[3];
    const float* r_b2    = (const float*)d_in[4];
    const float* r_w3    = (const float*)d_in[5];
    const float* r_b3    = (const float*)d_in[6];
    const float* temp    = (const float*)d_in[7];
    const float* pre_w   = (const float*)d_in[8];
    const float* pre_b   = (const float*)d_in[9];
    const float* pre_g   = (const float*)d_in[10];
    const float* pre_be  = (const float*)d_in[11];
    const float* mlp_w1  = (const float*)d_in[12];
    const float* mlp_b1  = (const float*)d_in[13];
    const float* mlp_w2  = (const float*)d_in[14];
    const float* mlp_b2  = (const float*)d_in[15];
    const float* post_w  = (const float*)d_in[16];
    const float* post_b  = (const float*)d_in[17];
    const float* post_g  = (const float*)d_in[18];
    const float* post_be = (const float*)d_in[19];
    float* out = (float*)d_out;

    float *h1, *h2, *sc, *preu, *xin, *hmid, *y, *z, *w;
    int *prei, *posti, *cnt, *rows;
    cudaGetSymbolAddress((void**)&h1, g_h1);
    cudaGetSymbolAddress((void**)&h2, g_h2);
    cudaGetSymbolAddress((void**)&sc, g_scores);
    cudaGetSymbolAddress((void**)&preu, g_preu);
    cudaGetSymbolAddress((void**)&xin, g_xin);
    cudaGetSymbolAddress((void**)&hmid, g_hmid);
    cudaGetSymbolAddress((void**)&y, g_y);
    cudaGetSymbolAddress((void**)&z, g_z);
    cudaGetSymbolAddress((void**)&w, g_w);
    cudaGetSymbolAddress((void**)&prei, g_prei);
    cudaGetSymbolAddress((void**)&posti, g_posti);
    cudaGetSymbolAddress((void**)&cnt, g_cnt);
    cudaGetSymbolAddress((void**)&rows, g_rows);

    zero_k<<<1, 64>>>(cnt);

    // router (exact fp32 — protects top-k indices)
    {
        GArgs a = {x, D, r_w1, 0, 512, r_b1, 0, h1, 512,
                   T, 512, 512, nullptr, nullptr, 0, 0, 0, 1};
        gemm_k<<<dim3(8, 4, 1), 256>>>(a);
    }
    {
        GArgs a = {h1, 512, r_w2, 0, 256, r_b2, 0, h2, 256,
                   T, 256, 512, nullptr, nullptr, 0, 0, 0, 1};
        gemm_k<<<dim3(4, 4, 1), 256>>>(a);
    }
    {
        GArgs a = {h2, 256, r_w3, 0, NSCORE, r_b3, 0, sc, NSCORE,
                   T, NSCORE, 256, nullptr, nullptr, 0, 0, 0, 0};
        gemm_k<<<dim3(64, 4, 1), 256>>>(a);
    }

    route_k<<<T, 256>>>(sc, temp, w, prei, posti, cnt, rows);

    // experts: tf32 tensor cores, grouped + gathered
    {
        GArgs a = {x, D, pre_w, (long)D * D, D, pre_b, D, preu, D,
                   NPAIR, D, D, rows, cnt, 3, 0, 0, 0};
        tgemm_k<<<dim3(8, 4, NEXP), 128>>>(a);
    }
    prelnact_k<<<NPAIR, 256>>>(preu, prei, pre_g, pre_be, xin);

    {
        GArgs a = {xin, D, mlp_w1, (long)D * MAXH, MAXH, mlp_b1, MAXH, hmid, MAXH,
                   NPAIR, MAXH, D, rows + 16 * NPAIR, cnt + 16, 0, 1, 0, 5};
        tgemm_k<<<dim3(40, 4, NEXP), 128>>>(a);
    }
    {
        GArgs a = {hmid, MAXH, mlp_w2, (long)MAXH * D, D, mlp_b2, D, y, D,
                   NPAIR, D, MAXH, rows + 16 * NPAIR, cnt + 16, 0, 0, 1, 0};
        tgemm_k<<<dim3(8, 4, NEXP), 128>>>(a);
    }
    {
        GArgs a = {y, D, post_w, (long)D * D, D, post_b, D, z, D,
                   NPAIR, D, D, rows + 32 * NPAIR, cnt + 32, 0, 0, 0, 0};
        tgemm_k<<<dim3(8, 4, NEXP), 128>>>(a);
    }

    final_k<<<T, 256>>>(z, posti, w, post_g, post_be, out);
}